// round 14
// baseline (speedup 1.0000x reference)
#include <cuda_runtime.h>
#include <cuda_fp16.h>
#include <cstdint>
#include <math.h>

#define B_ 8
#define S_ 2048
#define D_ 768
#define DK_ 768
#define MTOT (B_ * S_)   // 16384
#define EPS_ 1e-5f

// ---------------- scratch (device globals; no allocations allowed) ----------
__device__ __align__(16) __half g_srch[(size_t)MTOT * D_];
__device__ __align__(16) __half g_QKV[(size_t)3 * MTOT * DK_];   // Q|K|V packed
__device__ __align__(16) __half g_Wh3[(size_t)3 * D_ * DK_];     // Wq|Wk|Wv packed
__device__ __align__(16) __half g_Woh[DK_ * D_];
__device__ __align__(16) __half g_Sch[(size_t)B_ * S_ * S_];     // exp(scores) fp16
__device__ __align__(16) __half g_ctxh[(size_t)MTOT * DK_];
__device__ __align__(16) __half g_aoh[(size_t)MTOT * D_];
__device__ float g_rowsum[(size_t)B_ * S_];                      // attn row sums
__device__ float g_pooled[B_ * D_];

// ---------------- helpers ----------------------------------------------------
__device__ __forceinline__ void cp_async16(void* sp, const void* gp) {
    unsigned s = (unsigned)__cvta_generic_to_shared(sp);
    asm volatile("cp.async.cg.shared.global [%0], [%1], 16;\n" :: "r"(s), "l"(gp));
}
__device__ __forceinline__ void mma_f16(float* d, const uint32_t* a, const uint32_t* b) {
    asm volatile(
        "mma.sync.aligned.m16n8k16.row.col.f32.f16.f16.f32 "
        "{%0,%1,%2,%3}, {%4,%5,%6,%7}, {%8,%9}, {%0,%1,%2,%3};"
        : "+f"(d[0]), "+f"(d[1]), "+f"(d[2]), "+f"(d[3])
        : "r"(a[0]), "r"(a[1]), "r"(a[2]), "r"(a[3]), "r"(b[0]), "r"(b[1]));
}
__device__ __forceinline__ void ldsm_x4(uint32_t& r0, uint32_t& r1, uint32_t& r2,
                                        uint32_t& r3, uint32_t addr) {
    asm volatile("ldmatrix.sync.aligned.m8n8.x4.shared.b16 {%0,%1,%2,%3}, [%4];"
                 : "=r"(r0), "=r"(r1), "=r"(r2), "=r"(r3) : "r"(addr));
}
__device__ __forceinline__ void ldsm_x4_t(uint32_t& r0, uint32_t& r1, uint32_t& r2,
                                          uint32_t& r3, uint32_t addr) {
    asm volatile("ldmatrix.sync.aligned.m8n8.x4.trans.shared.b16 {%0,%1,%2,%3}, [%4];"
                 : "=r"(r0), "=r"(r1), "=r"(r2), "=r"(r3) : "r"(addr));
}

// ---------------- FP16 mma.sync GEMM (persistent tiles) -----------------------
// C[M,N] = f(alpha * A[M,K] @ B).  A half K-major.
// BMODE 0: B is [N,K] (K-major).  BMODE 1: B is [K,N] (ldmatrix.trans).
// EPI 1: half out.  EPI 2: half out = exp(alpha*acc), + per-row sum atomics.
// EPI 3: half out = acc / rowsum[row].
// 128x128 tile, BK=64, 3-stage cp.async (wait_group 1), 4 warps, 64x64/warp.
// Grid = 2*SMcount persistent CTAs looping over gx*gy*gz tiles.
#define RS_A 72
#define RS_BT 136
#define A_TILE_H (128 * RS_A)
#define B_TILE_H (128 * RS_A)
#define STAGE_H (A_TILE_H + B_TILE_H)
#define NSTAGE 3
#define GEMM_SMEM (NSTAGE * STAGE_H * 2)   // 110592 B

template <int BMODE, int EPI>
__global__ void __launch_bounds__(128, 2) gemm_h(
    const __half* __restrict__ Ag, const __half* __restrict__ Bg,
    void* __restrict__ Cv, int M, int N, int K, int ldB, float alpha,
    size_t sA, size_t sB, size_t sC, float* __restrict__ rowsumg, size_t sR,
    int gx, int gy, int gz)
{
    extern __shared__ __half smem[];

    const int tid = threadIdx.x;
    const int wid = tid >> 5;
    const int lane = tid & 31;
    const int gid = lane >> 2;
    const int tig = lane & 3;
    const int mat = lane >> 3;
    const int rw = lane & 7;
    const int wm = wid & 1;
    const int wn = wid >> 1;
    const uint32_t smem_base = (uint32_t)__cvta_generic_to_shared(smem);

    const int nt = gx * gy * gz;
    for (int tile = blockIdx.x; tile < nt; tile += gridDim.x) {
        const int z = tile / (gx * gy);
        const int rem = tile - z * gx * gy;
        const int m0 = (rem / gx) * 128;
        const int n0 = (rem - (rem / gx) * gx) * 128;

        const __half* A  = Ag + z * sA;
        const __half* Bm = Bg + z * sB;

        float acc[4][8][4];
        #pragma unroll
        for (int i = 0; i < 4; i++)
            #pragma unroll
            for (int j = 0; j < 8; j++)
                #pragma unroll
                for (int t = 0; t < 4; t++) acc[i][j][t] = 0.0f;

        auto load_tile = [&](int t, int st) {
            __half* sa = smem + st * STAGE_H;
            __half* sb = sa + A_TILE_H;
            const int k0 = t * 64;
            #pragma unroll
            for (int i = 0; i < 8; i++) {
                int id = i * 128 + tid;
                int row = id >> 3, c8 = (id & 7) * 8;
                cp_async16(sa + row * RS_A + c8, A + (size_t)(m0 + row) * K + k0 + c8);
            }
            if (BMODE == 0) {
                #pragma unroll
                for (int i = 0; i < 8; i++) {
                    int id = i * 128 + tid;
                    int row = id >> 3, c8 = (id & 7) * 8;
                    cp_async16(sb + row * RS_A + c8, Bm + (size_t)(n0 + row) * ldB + k0 + c8);
                }
            } else {
                #pragma unroll
                for (int i = 0; i < 8; i++) {
                    int id = i * 128 + tid;
                    int row = id >> 4, c8 = (id & 15) * 8;
                    cp_async16(sb + row * RS_BT + c8, Bm + (size_t)(k0 + row) * ldB + n0 + c8);
                }
            }
            asm volatile("cp.async.commit_group;\n" ::);
        };

        auto compute = [&](int st) {
            const uint32_t sa = smem_base + (uint32_t)(st * STAGE_H) * 2u;
            const uint32_t sb = sa + A_TILE_H * 2u;
            #pragma unroll
            for (int k16 = 0; k16 < 4; k16++) {
                const int kb = k16 * 16;
                uint32_t af[4][4];
                #pragma unroll
                for (int i = 0; i < 4; i++) {
                    uint32_t addr = sa + 2u * ((wm * 64 + i * 16 + (mat & 1) * 8 + rw) * RS_A
                                               + kb + (mat >> 1) * 8);
                    ldsm_x4(af[i][0], af[i][1], af[i][2], af[i][3], addr);
                }
                uint32_t bf[8][2];
                #pragma unroll
                for (int jp = 0; jp < 4; jp++) {
                    const int n = wn * 64 + jp * 16;
                    if (BMODE == 0) {
                        uint32_t addr = sb + 2u * ((n + (mat >> 1) * 8 + rw) * RS_A
                                                   + kb + (mat & 1) * 8);
                        ldsm_x4(bf[2 * jp][0], bf[2 * jp][1], bf[2 * jp + 1][0],
                                bf[2 * jp + 1][1], addr);
                    } else {
                        uint32_t addr = sb + 2u * ((kb + (mat & 1) * 8 + rw) * RS_BT
                                                   + n + (mat >> 1) * 8);
                        ldsm_x4_t(bf[2 * jp][0], bf[2 * jp][1], bf[2 * jp + 1][0],
                                  bf[2 * jp + 1][1], addr);
                    }
                }
                #pragma unroll
                for (int i = 0; i < 4; i++)
                    #pragma unroll
                    for (int j = 0; j < 8; j++)
                        mma_f16(acc[i][j], af[i], bf[j]);
            }
        };

        const int nk = K / 64;
        load_tile(0, 0);
        if (nk > 1) load_tile(1, 1);

        int st = 0;
        for (int s = 0; s < nk; s++) {
            if (s < nk - 1) asm volatile("cp.async.wait_group 1;\n" ::);
            else            asm volatile("cp.async.wait_group 0;\n" ::);
            __syncthreads();
            if (s + 2 < nk) {
                int st2 = st + 2; if (st2 >= NSTAGE) st2 -= NSTAGE;
                load_tile(s + 2, st2);
            }
            compute(st);
            if (++st == NSTAGE) st = 0;
        }

        // ---------------- epilogue ----------------
        __half* C = (__half*)Cv + z * sC;

        if (EPI == 1) {
            #pragma unroll
            for (int i = 0; i < 4; i++) {
                const int rbase = m0 + wm * 64 + i * 16 + gid;
                #pragma unroll
                for (int j = 0; j < 8; j++) {
                    const int col = n0 + wn * 64 + j * 8 + tig * 2;
                    *(__half2*)(C + (size_t)rbase * N + col) =
                        __floats2half2_rn(acc[i][j][0] * alpha, acc[i][j][1] * alpha);
                    *(__half2*)(C + (size_t)(rbase + 8) * N + col) =
                        __floats2half2_rn(acc[i][j][2] * alpha, acc[i][j][3] * alpha);
                }
            }
        } else if (EPI == 2) {
            float* rs = rowsumg + z * sR;
            #pragma unroll
            for (int i = 0; i < 4; i++) {
                const int r0 = m0 + wm * 64 + i * 16 + gid;
                float s0 = 0.0f, s1 = 0.0f;
                #pragma unroll
                for (int j = 0; j < 8; j++) {
                    const int col = n0 + wn * 64 + j * 8 + tig * 2;
                    float e0 = __expf(acc[i][j][0] * alpha);
                    float e1 = __expf(acc[i][j][1] * alpha);
                    float e2 = __expf(acc[i][j][2] * alpha);
                    float e3 = __expf(acc[i][j][3] * alpha);
                    s0 += e0 + e1;
                    s1 += e2 + e3;
                    *(__half2*)(C + (size_t)r0 * N + col)       = __floats2half2_rn(e0, e1);
                    *(__half2*)(C + (size_t)(r0 + 8) * N + col) = __floats2half2_rn(e2, e3);
                }
                s0 += __shfl_xor_sync(0xFFFFFFFFu, s0, 1);
                s0 += __shfl_xor_sync(0xFFFFFFFFu, s0, 2);
                s1 += __shfl_xor_sync(0xFFFFFFFFu, s1, 1);
                s1 += __shfl_xor_sync(0xFFFFFFFFu, s1, 2);
                if (tig == 0) {
                    atomicAdd(rs + r0, s0);
                    atomicAdd(rs + r0 + 8, s1);
                }
            }
        } else {  // EPI == 3
            const float* rs = rowsumg + z * sR;
            #pragma unroll
            for (int i = 0; i < 4; i++) {
                const int r0 = m0 + wm * 64 + i * 16 + gid;
                const float inv0 = __fdividef(1.0f, rs[r0]);
                const float inv1 = __fdividef(1.0f, rs[r0 + 8]);
                #pragma unroll
                for (int j = 0; j < 8; j++) {
                    const int col = n0 + wn * 64 + j * 8 + tig * 2;
                    *(__half2*)(C + (size_t)r0 * N + col) =
                        __floats2half2_rn(acc[i][j][0] * inv0, acc[i][j][1] * inv0);
                    *(__half2*)(C + (size_t)(r0 + 8) * N + col) =
                        __floats2half2_rn(acc[i][j][2] * inv1, acc[i][j][3] * inv1);
                }
            }
        }
        __syncthreads();   // protect smem stages before next tile's loads
    }
}

// ---------------- fp32 -> fp16 ------------------------------------------------
__global__ void __launch_bounds__(256) f2h_kernel(const float* __restrict__ in,
                                                  __half* __restrict__ out, int n4) {
    int i = blockIdx.x * 256 + threadIdx.x;
    if (i < n4) {
        float4 v = ((const float4*)in)[i];
        ((__half2*)out)[2 * i]     = __floats2half2_rn(v.x, v.y);
        ((__half2*)out)[2 * i + 1] = __floats2half2_rn(v.z, v.w);
    }
}

// 4 weight matrices in one launch (blockIdx.y selects)
__global__ void __launch_bounds__(256) f2h4_kernel(
    const float* __restrict__ w0, const float* __restrict__ w1,
    const float* __restrict__ w2, const float* __restrict__ w3,
    __half* __restrict__ o0, __half* __restrict__ o1,
    __half* __restrict__ o2, __half* __restrict__ o3, int n4)
{
    const float* in;
    __half* out;
    switch (blockIdx.y) {
        case 0: in = w0; out = o0; break;
        case 1: in = w1; out = o1; break;
        case 2: in = w2; out = o2; break;
        default: in = w3; out = o3; break;
    }
    int i = blockIdx.x * 256 + threadIdx.x;
    if (i < n4) {
        float4 v = ((const float4*)in)[i];
        ((__half2*)out)[2 * i]     = __floats2half2_rn(v.x, v.y);
        ((__half2*)out)[2 * i + 1] = __floats2half2_rn(v.z, v.w);
    }
}

// ---------------- zero rowsum + pooled (one launch) ---------------------------
__global__ void __launch_bounds__(256) zero_kernel(float* __restrict__ rs,
                                                   float* __restrict__ pooled) {
    int i = blockIdx.x * 256 + threadIdx.x;
    if (i < B_ * S_) rs[i] = 0.0f;
    if (i < B_ * D_) pooled[i] = 0.0f;
}

// ---------------- warp reductions --------------------------------------------
__device__ __forceinline__ float warp_sum(float v) {
    #pragma unroll
    for (int o = 16; o > 0; o >>= 1) v += __shfl_xor_sync(0xFFFFFFFFu, v, o);
    return v;
}
__device__ __forceinline__ float block_sum(float v, float* sh) {
    __syncthreads();
    int lane = threadIdx.x & 31, w = threadIdx.x >> 5;
    v = warp_sum(v);
    if (lane == 0) sh[w] = v;
    __syncthreads();
    float r = (threadIdx.x < (blockDim.x >> 5)) ? sh[threadIdx.x] : 0.0f;
    if (w == 0) {
        r = warp_sum(r);
        if (lane == 0) sh[0] = r;
    }
    __syncthreads();
    return sh[0];
}

// ---------------- residual(+bo) + LN + LN + pooled partial, fused -------------
__global__ void __launch_bounds__(256) resid_ln2_pool_kernel(
    const float* __restrict__ src, const __half* __restrict__ ao,
    const float* __restrict__ bo,
    const float* __restrict__ w1, const float* __restrict__ b1,
    const float* __restrict__ w2, const float* __restrict__ b2,
    float* __restrict__ xout, float* __restrict__ pooled)
{
    __shared__ float sp[8][D_];
    const int w = threadIdx.x >> 5;
    const int lane = threadIdx.x & 31;
    const size_t row = (size_t)blockIdx.x * 8 + w;
    const int b = (int)(row / S_);
    const size_t base = row * (size_t)D_;

    float v[24];
    float s = 0.0f;
    #pragma unroll
    for (int i = 0; i < 24; i++) {
        const int d = lane + 32 * i;
        v[i] = src[base + d] + __half2float(ao[base + d]) + bo[d];
        s += v[i];
    }
    s = warp_sum(s);
    const float mu1 = s * (1.0f / (float)D_);
    float sq = 0.0f;
    #pragma unroll
    for (int i = 0; i < 24; i++) { float t = v[i] - mu1; sq += t * t; }
    sq = warp_sum(sq);
    const float r1 = rsqrtf(sq * (1.0f / (float)D_) + EPS_);
    s = 0.0f;
    #pragma unroll
    for (int i = 0; i < 24; i++) {
        const int d = lane + 32 * i;
        v[i] = (v[i] - mu1) * r1 * w1[d] + b1[d];
        s += v[i];
    }
    s = warp_sum(s);
    const float mu2 = s * (1.0f / (float)D_);
    sq = 0.0f;
    #pragma unroll
    for (int i = 0; i < 24; i++) { float t = v[i] - mu2; sq += t * t; }
    sq = warp_sum(sq);
    const float r2 = rsqrtf(sq * (1.0f / (float)D_) + EPS_);
    #pragma unroll
    for (int i = 0; i < 24; i++) {
        const int d = lane + 32 * i;
        const float x = (v[i] - mu2) * r2 * w2[d] + b2[d];
        xout[base + d] = x;
        sp[w][d] = x;
    }
    __syncthreads();

    #pragma unroll
    for (int j = 0; j < 3; j++) {
        const int d = threadIdx.x + 256 * j;
        float acc = sp[0][d];
        #pragma unroll
        for (int r = 1; r < 8; r++) acc += sp[r][d];
        atomicAdd(pooled + b * D_ + d, acc * (1.0f / (float)S_));
    }
}

// ---------------- logits -----------------------------------------------------
__global__ void __launch_bounds__(128) logits_kernel(
    const float* __restrict__ pooled, const float* __restrict__ Wc,
    const float* __restrict__ bc, float* __restrict__ out)
{
    __shared__ float sh[32];
    const int idx = blockIdx.x;
    const int b = idx / 10, o = idx % 10;
    float s = 0.0f;
    for (int dd = threadIdx.x; dd < D_; dd += 128)
        s += pooled[b * D_ + dd] * Wc[dd * 10 + o];
    s = block_sum(s, sh);
    if (threadIdx.x == 0) out[b * 10 + o] = s + bc[o];
}

// ---------------- launch -----------------------------------------------------
extern "C" void kernel_launch(void* const* d_in, const int* in_sizes, int n_in,
                              void* d_out, int out_size) {
    const float* src  = (const float*)d_in[0];
    const float* Wq   = (const float*)d_in[1];
    const float* Wk   = (const float*)d_in[2];
    const float* Wv   = (const float*)d_in[3];
    const float* Wo   = (const float*)d_in[4];
    const float* bo   = (const float*)d_in[5];
    const float* ln1w = (const float*)d_in[6];
    const float* ln1b = (const float*)d_in[7];
    const float* ln2w = (const float*)d_in[8];
    const float* ln2b = (const float*)d_in[9];
    const float* Wc   = (const float*)d_in[10];
    const float* bc   = (const float*)d_in[11];

    float* out    = (float*)d_out;
    float* logits = out;           // [8,10]
    float* xout   = out + B_ * 10; // [8,2048,768]

    __half *srch, *QKV, *Wh3, *Woh, *Sch, *ctxh, *aoh;
    float *rowsum, *pooled;
    cudaGetSymbolAddress((void**)&srch,   g_srch);
    cudaGetSymbolAddress((void**)&QKV,    g_QKV);
    cudaGetSymbolAddress((void**)&Wh3,    g_Wh3);
    cudaGetSymbolAddress((void**)&Woh,    g_Woh);
    cudaGetSymbolAddress((void**)&Sch,    g_Sch);
    cudaGetSymbolAddress((void**)&ctxh,   g_ctxh);
    cudaGetSymbolAddress((void**)&aoh,    g_aoh);
    cudaGetSymbolAddress((void**)&rowsum, g_rowsum);
    cudaGetSymbolAddress((void**)&pooled, g_pooled);

    __half* Qh = QKV;
    __half* Kh = QKV + (size_t)MTOT * DK_;
    __half* Vh = QKV + (size_t)2 * MTOT * DK_;

    int nsm = 148;
    cudaDeviceGetAttribute(&nsm, cudaDevAttrMultiProcessorCount, 0);
    const int NP = 2 * nsm;   // persistent CTAs (2 per SM)

    cudaFuncSetAttribute(gemm_h<1, 1>, cudaFuncAttributeMaxDynamicSharedMemorySize, GEMM_SMEM);
    cudaFuncSetAttribute(gemm_h<0, 2>, cudaFuncAttributeMaxDynamicSharedMemorySize, GEMM_SMEM);
    cudaFuncSetAttribute(gemm_h<1, 3>, cudaFuncAttributeMaxDynamicSharedMemorySize, GEMM_SMEM);

    // 0) fp32 -> fp16 conversions; zero row sums + pooled
    f2h_kernel<<<(MTOT * D_ / 4 + 255) / 256, 256>>>(src, srch, MTOT * D_ / 4);
    {
        const int n4 = D_ * DK_ / 4;
        dim3 grid((n4 + 255) / 256, 4);
        f2h4_kernel<<<grid, 256>>>(Wq, Wk, Wv, Wo,
                                   Wh3, Wh3 + (size_t)D_ * DK_,
                                   Wh3 + (size_t)2 * D_ * DK_, Woh, n4);
    }
    zero_kernel<<<(B_ * S_ + 255) / 256, 256>>>(rowsum, pooled);

    // 1) Q,K,V = src @ W*  (tiles: gx=6, gy=128, gz=3)
    gemm_h<1, 1><<<NP, 128, GEMM_SMEM>>>(
        srch, Wh3, QKV, MTOT, DK_, D_, DK_, 1.0f,
        0, (size_t)D_ * DK_, (size_t)MTOT * DK_, nullptr, 0,
        DK_ / 128, MTOT / 128, 3);

    // 2) probs_unnorm = exp(Q @ K^T / sqrt(DK)) + row sums  (gx=16, gy=16, gz=8)
    {
        const float alpha = rsqrtf((float)DK_);
        gemm_h<0, 2><<<NP, 128, GEMM_SMEM>>>(
            Qh, Kh, Sch, S_, S_, DK_, DK_, alpha,
            (size_t)S_ * DK_, (size_t)S_ * DK_, (size_t)S_ * S_, rowsum, S_,
            S_ / 128, S_ / 128, B_);
    }
    // 3) ctx = (e @ V) / rowsum  (gx=6, gy=16, gz=8)
    gemm_h<1, 3><<<NP, 128, GEMM_SMEM>>>(
        Sch, Vh, ctxh, S_, DK_, S_, DK_, 1.0f,
        (size_t)S_ * S_, (size_t)S_ * DK_, (size_t)S_ * DK_, rowsum, S_,
        DK_ / 128, S_ / 128, B_);

    // 4) ao = ctx @ Wo  (gx=6, gy=128, gz=1)
    gemm_h<1, 1><<<NP, 128, GEMM_SMEM>>>(
        ctxh, Woh, aoh, MTOT, D_, DK_, D_, 1.0f, 0, 0, 0, nullptr, 0,
        D_ / 128, MTOT / 128, 1);

    // 5) x = LN2(LN1(src + ao + bo)) + fused pooled partials
    resid_ln2_pool_kernel<<<MTOT / 8, 256>>>(src, aoh, bo, ln1w, ln1b,
                                             ln2w, ln2b, xout, pooled);
    // 6) logits
    logits_kernel<<<B_ * 10, 128>>>(pooled, Wc, bc, logits);
}

// round 15
// speedup vs baseline: 1.0314x; 1.0314x over previous
#include <cuda_runtime.h>
#include <cuda_fp16.h>
#include <cstdint>
#include <math.h>

#define B_ 8
#define S_ 2048
#define D_ 768
#define DK_ 768
#define MTOT (B_ * S_)   // 16384
#define EPS_ 1e-5f

// ---------------- scratch (device globals; no allocations allowed) ----------
__device__ __align__(16) __half g_srch[(size_t)MTOT * D_];
__device__ __align__(16) __half g_QKV[(size_t)3 * MTOT * DK_];   // Q|K|V packed
__device__ __align__(16) __half g_Wh3[(size_t)3 * D_ * DK_];     // Wq|Wk|Wv packed
__device__ __align__(16) __half g_Woh[DK_ * D_];
__device__ __align__(16) __half g_Sch[(size_t)B_ * S_ * S_];     // exp(scores) fp16
__device__ __align__(16) __half g_ctxh[(size_t)MTOT * DK_];
__device__ __align__(16) __half g_aoh[(size_t)MTOT * D_];
__device__ float g_rowsum[(size_t)B_ * S_];                      // attn row sums
__device__ float g_pooled[B_ * D_];

// ---------------- helpers ----------------------------------------------------
__device__ __forceinline__ void cp_async16(void* sp, const void* gp) {
    unsigned s = (unsigned)__cvta_generic_to_shared(sp);
    asm volatile("cp.async.cg.shared.global [%0], [%1], 16;\n" :: "r"(s), "l"(gp));
}
__device__ __forceinline__ void mma_f16(float* d, const uint32_t* a, const uint32_t* b) {
    asm volatile(
        "mma.sync.aligned.m16n8k16.row.col.f32.f16.f16.f32 "
        "{%0,%1,%2,%3}, {%4,%5,%6,%7}, {%8,%9}, {%0,%1,%2,%3};"
        : "+f"(d[0]), "+f"(d[1]), "+f"(d[2]), "+f"(d[3])
        : "r"(a[0]), "r"(a[1]), "r"(a[2]), "r"(a[3]), "r"(b[0]), "r"(b[1]));
}
__device__ __forceinline__ void ldsm_x4(uint32_t& r0, uint32_t& r1, uint32_t& r2,
                                        uint32_t& r3, uint32_t addr) {
    asm volatile("ldmatrix.sync.aligned.m8n8.x4.shared.b16 {%0,%1,%2,%3}, [%4];"
                 : "=r"(r0), "=r"(r1), "=r"(r2), "=r"(r3) : "r"(addr));
}
__device__ __forceinline__ void ldsm_x4_t(uint32_t& r0, uint32_t& r1, uint32_t& r2,
                                          uint32_t& r3, uint32_t addr) {
    asm volatile("ldmatrix.sync.aligned.m8n8.x4.trans.shared.b16 {%0,%1,%2,%3}, [%4];"
                 : "=r"(r0), "=r"(r1), "=r"(r2), "=r"(r3) : "r"(addr));
}

// ---------------- FP16 mma.sync GEMM -----------------------------------------
// C[M,N] = f(alpha * A[M,K] @ B).  A half K-major.
// BMODE 0: B is [N,K] (K-major).  BMODE 1: B is [K,N] (ldmatrix.trans).
// EPI 1: half out.  EPI 2: half out = exp(alpha*acc), + per-row sum atomics.
// EPI 3: half out = acc / rowsum[row].
// 128x128 CTA tile, BK=64, 3-stage cp.async (wait_group 1), 4 warps, 64x64/warp.
#define RS_A 72
#define RS_BT 136
#define A_TILE_H (128 * RS_A)
#define B_TILE_H (128 * RS_A)
#define STAGE_H (A_TILE_H + B_TILE_H)
#define NSTAGE 3
#define GEMM_SMEM (NSTAGE * STAGE_H * 2)   // 110592 B

template <int BMODE, int EPI>
__global__ void __launch_bounds__(128, 2) gemm_h(
    const __half* __restrict__ A, const __half* __restrict__ Bm,
    void* __restrict__ Cv, int M, int N, int K, int ldB, float alpha,
    size_t sA, size_t sB, size_t sC, float* __restrict__ rowsum, size_t sR)
{
    extern __shared__ __half smem[];

    A  += blockIdx.z * sA;
    Bm += blockIdx.z * sB;

    const int tid = threadIdx.x;
    const int wid = tid >> 5;
    const int lane = tid & 31;
    const int gid = lane >> 2;
    const int tig = lane & 3;
    const int mat = lane >> 3;
    const int rw = lane & 7;
    const int wm = wid & 1;
    const int wn = wid >> 1;
    const int m0 = blockIdx.y * 128;
    const int n0 = blockIdx.x * 128;

    const uint32_t smem_base = (uint32_t)__cvta_generic_to_shared(smem);

    float acc[4][8][4];
    #pragma unroll
    for (int i = 0; i < 4; i++)
        #pragma unroll
        for (int j = 0; j < 8; j++)
            #pragma unroll
            for (int t = 0; t < 4; t++) acc[i][j][t] = 0.0f;

    auto load_tile = [&](int t, int st) {
        __half* sa = smem + st * STAGE_H;
        __half* sb = sa + A_TILE_H;
        const int k0 = t * 64;
        #pragma unroll
        for (int i = 0; i < 8; i++) {
            int id = i * 128 + tid;
            int row = id >> 3, c8 = (id & 7) * 8;
            cp_async16(sa + row * RS_A + c8, A + (size_t)(m0 + row) * K + k0 + c8);
        }
        if (BMODE == 0) {
            #pragma unroll
            for (int i = 0; i < 8; i++) {
                int id = i * 128 + tid;
                int row = id >> 3, c8 = (id & 7) * 8;
                cp_async16(sb + row * RS_A + c8, Bm + (size_t)(n0 + row) * ldB + k0 + c8);
            }
        } else {
            #pragma unroll
            for (int i = 0; i < 8; i++) {
                int id = i * 128 + tid;
                int row = id >> 4, c8 = (id & 15) * 8;
                cp_async16(sb + row * RS_BT + c8, Bm + (size_t)(k0 + row) * ldB + n0 + c8);
            }
        }
        asm volatile("cp.async.commit_group;\n" ::);
    };

    auto compute = [&](int st) {
        const uint32_t sa = smem_base + (uint32_t)(st * STAGE_H) * 2u;
        const uint32_t sb = sa + A_TILE_H * 2u;
        #pragma unroll
        for (int k16 = 0; k16 < 4; k16++) {
            const int kb = k16 * 16;
            uint32_t af[4][4];
            #pragma unroll
            for (int i = 0; i < 4; i++) {
                uint32_t addr = sa + 2u * ((wm * 64 + i * 16 + (mat & 1) * 8 + rw) * RS_A
                                           + kb + (mat >> 1) * 8);
                ldsm_x4(af[i][0], af[i][1], af[i][2], af[i][3], addr);
            }
            uint32_t bf[8][2];
            #pragma unroll
            for (int jp = 0; jp < 4; jp++) {
                const int n = wn * 64 + jp * 16;
                if (BMODE == 0) {
                    uint32_t addr = sb + 2u * ((n + (mat >> 1) * 8 + rw) * RS_A
                                               + kb + (mat & 1) * 8);
                    ldsm_x4(bf[2 * jp][0], bf[2 * jp][1], bf[2 * jp + 1][0],
                            bf[2 * jp + 1][1], addr);
                } else {
                    uint32_t addr = sb + 2u * ((kb + (mat & 1) * 8 + rw) * RS_BT
                                               + n + (mat >> 1) * 8);
                    ldsm_x4_t(bf[2 * jp][0], bf[2 * jp][1], bf[2 * jp + 1][0],
                              bf[2 * jp + 1][1], addr);
                }
            }
            #pragma unroll
            for (int i = 0; i < 4; i++)
                #pragma unroll
                for (int j = 0; j < 8; j++)
                    mma_f16(acc[i][j], af[i], bf[j]);
        }
    };

    const int nk = K / 64;
    load_tile(0, 0);
    if (nk > 1) load_tile(1, 1);

    int st = 0;
    for (int s = 0; s < nk; s++) {
        if (s < nk - 1) asm volatile("cp.async.wait_group 1;\n" ::);
        else            asm volatile("cp.async.wait_group 0;\n" ::);
        __syncthreads();
        if (s + 2 < nk) {
            int st2 = st + 2; if (st2 >= NSTAGE) st2 -= NSTAGE;
            load_tile(s + 2, st2);
        }
        compute(st);
        if (++st == NSTAGE) st = 0;
    }

    // ---------------- epilogue ----------------
    __half* C = (__half*)Cv + blockIdx.z * sC;

    if (EPI == 1) {
        #pragma unroll
        for (int i = 0; i < 4; i++) {
            const int rbase = m0 + wm * 64 + i * 16 + gid;
            #pragma unroll
            for (int j = 0; j < 8; j++) {
                const int col = n0 + wn * 64 + j * 8 + tig * 2;
                *(__half2*)(C + (size_t)rbase * N + col) =
                    __floats2half2_rn(acc[i][j][0] * alpha, acc[i][j][1] * alpha);
                *(__half2*)(C + (size_t)(rbase + 8) * N + col) =
                    __floats2half2_rn(acc[i][j][2] * alpha, acc[i][j][3] * alpha);
            }
        }
    } else if (EPI == 2) {
        float* rs = rowsum + blockIdx.z * sR;
        #pragma unroll
        for (int i = 0; i < 4; i++) {
            const int r0 = m0 + wm * 64 + i * 16 + gid;
            float s0 = 0.0f, s1 = 0.0f;
            #pragma unroll
            for (int j = 0; j < 8; j++) {
                const int col = n0 + wn * 64 + j * 8 + tig * 2;
                float e0 = __expf(acc[i][j][0] * alpha);
                float e1 = __expf(acc[i][j][1] * alpha);
                float e2 = __expf(acc[i][j][2] * alpha);
                float e3 = __expf(acc[i][j][3] * alpha);
                s0 += e0 + e1;
                s1 += e2 + e3;
                *(__half2*)(C + (size_t)r0 * N + col)       = __floats2half2_rn(e0, e1);
                *(__half2*)(C + (size_t)(r0 + 8) * N + col) = __floats2half2_rn(e2, e3);
            }
            s0 += __shfl_xor_sync(0xFFFFFFFFu, s0, 1);
            s0 += __shfl_xor_sync(0xFFFFFFFFu, s0, 2);
            s1 += __shfl_xor_sync(0xFFFFFFFFu, s1, 1);
            s1 += __shfl_xor_sync(0xFFFFFFFFu, s1, 2);
            if (tig == 0) {
                atomicAdd(rs + r0, s0);
                atomicAdd(rs + r0 + 8, s1);
            }
        }
    } else {  // EPI == 3
        const float* rs = rowsum + blockIdx.z * sR;
        #pragma unroll
        for (int i = 0; i < 4; i++) {
            const int r0 = m0 + wm * 64 + i * 16 + gid;
            const float inv0 = __fdividef(1.0f, rs[r0]);
            const float inv1 = __fdividef(1.0f, rs[r0 + 8]);
            #pragma unroll
            for (int j = 0; j < 8; j++) {
                const int col = n0 + wn * 64 + j * 8 + tig * 2;
                *(__half2*)(C + (size_t)r0 * N + col) =
                    __floats2half2_rn(acc[i][j][0] * inv0, acc[i][j][1] * inv0);
                *(__half2*)(C + (size_t)(r0 + 8) * N + col) =
                    __floats2half2_rn(acc[i][j][2] * inv1, acc[i][j][3] * inv1);
            }
        }
    }
}

// ---------------- merged prep: f2h(src) + f2h(4 weights) + zero fills ---------
#define NS4 (MTOT * D_ / 4)          // 3145728 float4 chunks for src
#define NW4 (D_ * DK_ / 4)           // 147456 per weight
__global__ void __launch_bounds__(256) prep_kernel(
    const float* __restrict__ src, const float* __restrict__ w0,
    const float* __restrict__ w1, const float* __restrict__ w2,
    const float* __restrict__ w3,
    __half* __restrict__ srch, __half* __restrict__ o0, __half* __restrict__ o1,
    __half* __restrict__ o2, __half* __restrict__ o3,
    float* __restrict__ rs, float* __restrict__ pooled)
{
    long idx = (long)blockIdx.x * 256 + threadIdx.x;

    // zero fills (overlap with first blocks' range, separate index space)
    if (idx < B_ * S_) rs[idx] = 0.0f;
    if (idx < B_ * D_) pooled[idx] = 0.0f;

    const float* in;
    __half* out;
    long i;
    if (idx < NS4) { in = src; out = srch; i = idx; }
    else {
        long r = idx - NS4;
        int w = (int)(r / NW4);
        i = r - (long)w * NW4;
        switch (w) {
            case 0: in = w0; out = o0; break;
            case 1: in = w1; out = o1; break;
            case 2: in = w2; out = o2; break;
            case 3: in = w3; out = o3; break;
            default: return;
        }
    }
    float4 v = ((const float4*)in)[i];
    ((__half2*)out)[2 * i]     = __floats2half2_rn(v.x, v.y);
    ((__half2*)out)[2 * i + 1] = __floats2half2_rn(v.z, v.w);
}

// ---------------- warp reductions --------------------------------------------
__device__ __forceinline__ float warp_sum(float v) {
    #pragma unroll
    for (int o = 16; o > 0; o >>= 1) v += __shfl_xor_sync(0xFFFFFFFFu, v, o);
    return v;
}

// ---------------- residual(+bo) + LN + LN + pooled partial, fused -------------
__global__ void __launch_bounds__(256) resid_ln2_pool_kernel(
    const float* __restrict__ src, const __half* __restrict__ ao,
    const float* __restrict__ bo,
    const float* __restrict__ w1, const float* __restrict__ b1,
    const float* __restrict__ w2, const float* __restrict__ b2,
    float* __restrict__ xout, float* __restrict__ pooled)
{
    __shared__ float sp[8][D_];
    const int w = threadIdx.x >> 5;
    const int lane = threadIdx.x & 31;
    const size_t row = (size_t)blockIdx.x * 8 + w;
    const int b = (int)(row / S_);
    const size_t base = row * (size_t)D_;

    float v[24];
    float s = 0.0f;
    #pragma unroll
    for (int i = 0; i < 24; i++) {
        const int d = lane + 32 * i;
        v[i] = src[base + d] + __half2float(ao[base + d]) + bo[d];
        s += v[i];
    }
    s = warp_sum(s);
    const float mu1 = s * (1.0f / (float)D_);
    float sq = 0.0f;
    #pragma unroll
    for (int i = 0; i < 24; i++) { float t = v[i] - mu1; sq += t * t; }
    sq = warp_sum(sq);
    const float r1 = rsqrtf(sq * (1.0f / (float)D_) + EPS_);
    s = 0.0f;
    #pragma unroll
    for (int i = 0; i < 24; i++) {
        const int d = lane + 32 * i;
        v[i] = (v[i] - mu1) * r1 * w1[d] + b1[d];
        s += v[i];
    }
    s = warp_sum(s);
    const float mu2 = s * (1.0f / (float)D_);
    sq = 0.0f;
    #pragma unroll
    for (int i = 0; i < 24; i++) { float t = v[i] - mu2; sq += t * t; }
    sq = warp_sum(sq);
    const float r2 = rsqrtf(sq * (1.0f / (float)D_) + EPS_);
    #pragma unroll
    for (int i = 0; i < 24; i++) {
        const int d = lane + 32 * i;
        const float x = (v[i] - mu2) * r2 * w2[d] + b2[d];
        xout[base + d] = x;
        sp[w][d] = x;
    }
    __syncthreads();

    #pragma unroll
    for (int j = 0; j < 3; j++) {
        const int d = threadIdx.x + 256 * j;
        float acc = sp[0][d];
        #pragma unroll
        for (int r = 1; r < 8; r++) acc += sp[r][d];
        atomicAdd(pooled + b * D_ + d, acc * (1.0f / (float)S_));
    }
}

// ---------------- logits: one warp per (b, o) ---------------------------------
__global__ void __launch_bounds__(32) logits_kernel(
    const float* __restrict__ pooled, const float* __restrict__ Wc,
    const float* __restrict__ bc, float* __restrict__ out)
{
    const int idx = blockIdx.x;       // 0..79
    const int b = idx / 10, o = idx % 10;
    float s = 0.0f;
    for (int dd = threadIdx.x; dd < D_; dd += 32)
        s += pooled[b * D_ + dd] * Wc[dd * 10 + o];
    s = warp_sum(s);
    if (threadIdx.x == 0) out[b * 10 + o] = s + bc[o];
}

// ---------------- launch -----------------------------------------------------
extern "C" void kernel_launch(void* const* d_in, const int* in_sizes, int n_in,
                              void* d_out, int out_size) {
    const float* src  = (const float*)d_in[0];
    const float* Wq   = (const float*)d_in[1];
    const float* Wk   = (const float*)d_in[2];
    const float* Wv   = (const float*)d_in[3];
    const float* Wo   = (const float*)d_in[4];
    const float* bo   = (const float*)d_in[5];
    const float* ln1w = (const float*)d_in[6];
    const float* ln1b = (const float*)d_in[7];
    const float* ln2w = (const float*)d_in[8];
    const float* ln2b = (const float*)d_in[9];
    const float* Wc   = (const float*)d_in[10];
    const float* bc   = (const float*)d_in[11];

    float* out    = (float*)d_out;
    float* logits = out;           // [8,10]
    float* xout   = out + B_ * 10; // [8,2048,768]

    __half *srch, *QKV, *Wh3, *Woh, *Sch, *ctxh, *aoh;
    float *rowsum, *pooled;
    cudaGetSymbolAddress((void**)&srch,   g_srch);
    cudaGetSymbolAddress((void**)&QKV,    g_QKV);
    cudaGetSymbolAddress((void**)&Wh3,    g_Wh3);
    cudaGetSymbolAddress((void**)&Woh,    g_Woh);
    cudaGetSymbolAddress((void**)&Sch,    g_Sch);
    cudaGetSymbolAddress((void**)&ctxh,   g_ctxh);
    cudaGetSymbolAddress((void**)&aoh,    g_aoh);
    cudaGetSymbolAddress((void**)&rowsum, g_rowsum);
    cudaGetSymbolAddress((void**)&pooled, g_pooled);

    __half* Qh = QKV;
    __half* Kh = QKV + (size_t)MTOT * DK_;
    __half* Vh = QKV + (size_t)2 * MTOT * DK_;

    cudaFuncSetAttribute(gemm_h<1, 1>, cudaFuncAttributeMaxDynamicSharedMemorySize, GEMM_SMEM);
    cudaFuncSetAttribute(gemm_h<0, 2>, cudaFuncAttributeMaxDynamicSharedMemorySize, GEMM_SMEM);
    cudaFuncSetAttribute(gemm_h<1, 3>, cudaFuncAttributeMaxDynamicSharedMemorySize, GEMM_SMEM);

    // 0) merged prep: f2h(src) + f2h(weights) + zero rowsum/pooled
    {
        const long total = (long)NS4 + 4L * NW4;
        prep_kernel<<<(unsigned)((total + 255) / 256), 256>>>(
            src, Wq, Wk, Wv, Wo,
            srch, Wh3, Wh3 + (size_t)D_ * DK_, Wh3 + (size_t)2 * D_ * DK_, Woh,
            rowsum, pooled);
    }

    // 1) Q,K,V = src @ W*  — single launch, z selects matrix
    {
        dim3 grid(DK_ / 128, MTOT / 128, 3);
        gemm_h<1, 1><<<grid, 128, GEMM_SMEM>>>(
            srch, Wh3, QKV, MTOT, DK_, D_, DK_, 1.0f,
            0, (size_t)D_ * DK_, (size_t)MTOT * DK_, nullptr, 0);
    }
    // 2) probs_unnorm = exp(Q @ K^T / sqrt(DK)), + row sums via atomics
    {
        dim3 grid(S_ / 128, S_ / 128, B_);
        const float alpha = rsqrtf((float)DK_);
        gemm_h<0, 2><<<grid, 128, GEMM_SMEM>>>(
            Qh, Kh, Sch, S_, S_, DK_, DK_, alpha,
            (size_t)S_ * DK_, (size_t)S_ * DK_, (size_t)S_ * S_, rowsum, S_);
    }
    // 3) ctx = (e @ V) / rowsum  (B = V [t,d] = [K,N] native)
    {
        dim3 grid(DK_ / 128, S_ / 128, B_);
        gemm_h<1, 3><<<grid, 128, GEMM_SMEM>>>(
            Sch, Vh, ctxh, S_, DK_, S_, DK_, 1.0f,
            (size_t)S_ * S_, (size_t)S_ * DK_, (size_t)S_ * DK_, rowsum, S_);
    }
    // 4) ao = ctx @ Wo  (half out; bo folded into resid)
    {
        dim3 grid(D_ / 128, MTOT / 128, 1);
        gemm_h<1, 1><<<grid, 128, GEMM_SMEM>>>(
            ctxh, Woh, aoh, MTOT, D_, DK_, D_, 1.0f, 0, 0, 0, nullptr, 0);
    }
    // 5) x = LN2(LN1(src + ao + bo)) + fused pooled partials
    resid_ln2_pool_kernel<<<MTOT / 8, 256>>>(src, aoh, bo, ln1w, ln1b,
                                             ln2w, ln2b, xout, pooled);
    // 6) logits
    logits_kernel<<<B_ * 10, 32>>>(pooled, Wc, bc, logits);
}